// round 12
// baseline (speedup 1.0000x reference)
#include <cuda_runtime.h>
#include <cuda_fp16.h>

#define TT 8
#define G  16
#define GG 256
#define DD 64
#define THRS 0.5f

// slot-spread accumulators: 0 wl, 1 pool, 2 obj, 3 pres, 4 flowsq, 5 sumzp, 6 sumflow
__device__ double g_slot[7][16];
__device__ unsigned g_ctr;

typedef unsigned long long u64;

__device__ __forceinline__ float wsum(float v) {
#pragma unroll
    for (int s = 16; s > 0; s >>= 1) v += __shfl_xor_sync(0xffffffffu, v, s);
    return v;
}

// ---- packed f32x2 helpers (exact wl path) ----
__device__ __forceinline__ u64 mkf(float lo, float hi) {
    u64 r; asm("mov.b64 %0, {%1, %2};" : "=l"(r) : "f"(lo), "f"(hi)); return r;
}
__device__ __forceinline__ u64 ffma2(u64 a, u64 b, u64 c) {
    u64 r; asm("fma.rn.f32x2 %0, %1, %2, %3;" : "=l"(r) : "l"(a), "l"(b), "l"(c)); return r;
}
__device__ __forceinline__ float lohisum(u64 v) {
    unsigned a, b; asm("mov.b64 {%0, %1}, %2;" : "=r"(a), "=r"(b) : "l"(v));
    return __uint_as_float(a) + __uint_as_float(b);
}

// ---- fp16x2 helpers ----
__device__ __forceinline__ unsigned pkh(float e0, float e1) {
    unsigned r;
    asm("cvt.rn.f16x2.f32 %0, %1, %2;" : "=r"(r) : "f"(e1), "f"(e0));
    return r;  // e0 lo half, e1 hi half
}
__device__ __forceinline__ unsigned hfma2(unsigned a, unsigned b, unsigned c) {
    unsigned r; asm("fma.rn.f16x2 %0, %1, %2, %3;" : "=r"(r) : "r"(a), "r"(b), "r"(c)); return r;
}
__device__ __forceinline__ unsigned hmul2(unsigned a, unsigned b) {
    unsigned r; asm("mul.rn.f16x2 %0, %1, %2;" : "=r"(r) : "r"(a), "r"(b)); return r;
}
__device__ __forceinline__ unsigned hmax2(unsigned a, unsigned b) {
    unsigned r; asm("max.f16x2 %0, %1, %2;" : "=r"(r) : "r"(a), "r"(b)); return r;
}
__device__ __forceinline__ float hsum(unsigned u) {
    float lo, hi;
    asm("{\n\t.reg .f16 a, b;\n\tmov.b32 {a, b}, %2;\n\tcvt.f32.f16 %0, a;\n\tcvt.f32.f16 %1, b;\n\t}"
        : "=f"(lo), "=f"(hi) : "r"(u));
    return lo + hi;
}

// swizzled uint4 index within a [GG][8]-uint4 frame (zero padding, conflict-free)
#define SWZ(cell, q) (((cell) << 3) + ((q) ^ ((cell) & 7)))

// s0 frame gets one extra all-zero row (cell index GG) for clamped pool neighbors
#define S0_ROWS (GG + 1)
#define SMEM_BYTES ((S0_ROWS * 8 + GG * 8) * 16 + 3 * GG * 4)  // 68,736 B -> 2 blocks/SM @512thr

// One block per (t,t+1,b) pair; 512 threads = (cell, D-half). Pres/flow folded in.
__global__ __launch_bounds__(512, 2) void fused_kernel(const float* __restrict__ zw,
                                                       const float* __restrict__ zp,
                                                       const float* __restrict__ fl,
                                                       const void* __restrict__ gs,
                                                       float* __restrict__ out,
                                                       int B, int npair) {
    extern __shared__ char smraw[];
    __shared__ double rd[7];
    __shared__ unsigned isLast;
    int tid = threadIdx.x;
    int blk = blockIdx.x;
    int slot = blk & 15;
    if (tid < 7) rd[tid] = 0.0;

    uint4* s0b = (uint4*)smraw;            // frame t fp16 [GG+1][8]; row GG = zeros
    uint4* s1b = s0b + S0_ROWS * 8;        // frame t+1 fp16 [GG][8]
    float* p0s = (float*)(s1b + GG * 8);
    float* p1s = p0s + GG;
    float* n1s = p1s + GG;                 // reciprocal norms of frame t+1 cells

    int b = blk % B, t = blk / B;
    size_t f0 = (size_t)(t * B + b);
    size_t f1 = f0 + B;
    const float4* g0 = (const float4*)(zw + f0 * (GG * DD));
    const float4* g1 = (const float4*)(zw + f1 * (GG * DD));

    if (tid < GG)            p0s[tid]      = zp[f0 * GG + tid];
    else                     p1s[tid - GG] = zp[f1 * GG + (tid - GG)];
    if (tid < 32) ((unsigned*)(s0b + GG * 8))[tid] = 0u;   // zero row

    // coalesced load: exact fp32 z_what_loss (packed) + swizzled fp16 frames
    const u64 NEG1 = 0xBF800000BF800000ULL;
    u64 wl2 = 0ULL;
#pragma unroll
    for (int it = 0; it < 8; ++it) {
        int idx = it * 512 + tid;
        float4 a = g0[idx];
        float4 v = g1[idx];
        u64 d01 = ffma2(mkf(a.x, a.y), NEG1, mkf(v.x, v.y));
        u64 d23 = ffma2(mkf(a.z, a.w), NEG1, mkf(v.z, v.w));
        wl2 = ffma2(d01, d01, wl2);
        wl2 = ffma2(d23, d23, wl2);
        int cell = idx >> 4, d4 = idx & 15;
        int u2idx = SWZ(cell, d4 >> 1) * 2 + (d4 & 1);
        uint2 pa, pb;
        pa.x = pkh(a.x, a.y);  pa.y = pkh(a.z, a.w);
        pb.x = pkh(v.x, v.y);  pb.y = pkh(v.z, v.w);
        ((uint2*)s0b)[u2idx] = pa;
        ((uint2*)s1b)[u2idx] = pb;
    }
    float wl = lohisum(wl2);
    __syncthreads();

    int c = tid >> 1, h = tid & 1;
    int qb = h << 2;                       // this thread's q range: qb..qb+3
    int i = c >> 4, j = c & 15;
    int cb = c << 3, cx = c & 7;
    float p0c = p0s[c], p1c = p1s[c];
    unsigned z0h = pkh(p0c, p0c);

    // ---- folded pres/flow terms (h == 0 threads only) ----
    float fsq = 0.f, szp = 0.f, sfl = 0.f, pres = 0.f;
    if (h == 0) {
        float f = fl[f0 * GG + c];
        float mx = -INFINITY;
#pragma unroll
        for (int di = -1; di <= 1; ++di) {
            int ii = i + di;
            if (ii < 0 || ii >= G) continue;
#pragma unroll
            for (int dj = -1; dj <= 1; ++dj) {
                int jj = j + dj;
                if (jj < 0 || jj >= G) continue;
                mx = fmaxf(mx, p0s[ii * G + jj]);
            }
        }
        fsq = (f > 0.5f) ? (mx - f) * (mx - f) : 0.f;
        szp = p0c;
        sfl = f;
        if (t >= 1) {   // pres triple centered at t
            float za = zp[(f0 - B) * GG + c];
            float zb = p1c;
            float dba = zb - za;
            float sim = 1.f - dba * dba;
            float d1 = zb - p0c, d2 = za - p0c;
            pres = sim * (d1 * d1 + d2 * d2);
        }
        if (t == TT - 2) {   // last pair block also handles image TT-1
            float f7 = fl[f1 * GG + c];
            float mx7 = -INFINITY;
#pragma unroll
            for (int di = -1; di <= 1; ++di) {
                int ii = i + di;
                if (ii < 0 || ii >= G) continue;
#pragma unroll
                for (int dj = -1; dj <= 1; ++dj) {
                    int jj = j + dj;
                    if (jj < 0 || jj >= G) continue;
                    mx7 = fmaxf(mx7, p1s[ii * G + jj]);
                }
            }
            fsq += (f7 > 0.5f) ? (mx7 - f7) * (mx7 - f7) : 0.f;
            szp += p1c;
            sfl += f7;
        }
    }

    // wrapped neighbor indexing (objects term, frame t+1) + pres mask
    int nb8[9];
    unsigned pmask = 0;
    {
        int k = 0;
#pragma unroll
        for (int di = -1; di <= 1; ++di)
#pragma unroll
            for (int dj = -1; dj <= 1; ++dj, ++k) {
                int nc = ((i + di) & 15) * 16 + ((j + dj) & 15);
                nb8[k] = nc << 3;
                if (p1s[nc] > THRS) pmask |= (1u << k);
            }
    }

    // ---- loop A: prior norm + 9 wrapped dots + in-place transform (half-D) ----
    float dotf[9];
    float pn;
    {
        unsigned dacc[9] = {0u, 0u, 0u, 0u, 0u, 0u, 0u, 0u, 0u};
        unsigned pna = 0u;
#pragma unroll
        for (int q = 0; q < 4; ++q) {
            int qq = qb + q;
            int off = qq ^ cx;
            uint4 pu = s0b[cb + off];
            const unsigned* pw = (const unsigned*)&pu;
            pna = hfma2(pw[0], pw[0], pna);
            pna = hfma2(pw[1], pw[1], pna);
            pna = hfma2(pw[2], pw[2], pna);
            pna = hfma2(pw[3], pw[3], pna);
#pragma unroll
            for (int k = 0; k < 9; ++k) {
                uint4 nu = s1b[nb8[k] + (qq ^ ((nb8[k] >> 3) & 7))];
                const unsigned* nw = (const unsigned*)&nu;
                unsigned d = dacc[k];
                d = hfma2(pw[0], nw[0], d);
                d = hfma2(pw[1], nw[1], d);
                d = hfma2(pw[2], nw[2], d);
                d = hfma2(pw[3], nw[3], d);
                dacc[k] = d;
            }
            uint4 tw;
            tw.x = hmul2(pw[0] & 0x7FFF7FFFu, z0h);
            tw.y = hmul2(pw[1] & 0x7FFF7FFFu, z0h);
            tw.z = hmul2(pw[2] & 0x7FFF7FFFu, z0h);
            tw.w = hmul2(pw[3] & 0x7FFF7FFFu, z0h);
            s0b[cb + off] = tw;
        }
        // combine half-D partials now (frees dacc registers before loop B)
#pragma unroll
        for (int k = 0; k < 9; ++k) {
            float d = hsum(dacc[k]);
            dotf[k] = d + __shfl_xor_sync(0xffffffffu, d, 1);
        }
        float p = hsum(pna);
        pn = p + __shfl_xor_sync(0xffffffffu, p, 1);
    }
    __syncthreads();   // all rows transformed

    // clamped pool indexing: out-of-grid -> zero row (cell GG)
    int cb8[9];
    {
        int k = 0;
#pragma unroll
        for (int di = -1; di <= 1; ++di)
#pragma unroll
            for (int dj = -1; dj <= 1; ++dj, ++k) {
                int ii = i + di, jj = j + dj;
                bool inb = (ii >= 0 && ii < G && jj >= 0 && jj < G);
                cb8[k] = (inb ? (ii * 16 + jj) : GG) << 3;
            }
    }

    // ---- loop B: 3x3 max of transformed s0 + pool partials (half-D, fp16x2) ----
    float cn, pd, na;
    {
        unsigned cna = 0u, pda = 0u, naa = 0u;
#pragma unroll
        for (int q = 0; q < 4; ++q) {
            int qq = qb + q;
            uint4 cu = s1b[cb + (qq ^ cx)];
            const unsigned* cw = (const unsigned*)&cu;
            unsigned ca[4];
#pragma unroll
            for (int w = 0; w < 4; ++w) {
                ca[w] = cw[w] & 0x7FFF7FFFu;
                cna = hfma2(ca[w], ca[w], cna);
            }
            unsigned mb0 = 0u, mb1 = 0u, mb2 = 0u, mb3 = 0u;
#pragma unroll
            for (int k = 0; k < 9; ++k) {
                uint4 su = s0b[cb8[k] + (qq ^ ((cb8[k] >> 3) & 7))];
                mb0 = hmax2(mb0, su.x);
                mb1 = hmax2(mb1, su.y);
                mb2 = hmax2(mb2, su.z);
                mb3 = hmax2(mb3, su.w);
            }
            pda = hfma2(mb0, ca[0], pda);
            naa = hfma2(mb0, mb0, naa);
            pda = hfma2(mb1, ca[1], pda);
            naa = hfma2(mb1, mb1, naa);
            pda = hfma2(mb2, ca[2], pda);
            naa = hfma2(mb2, mb2, naa);
            pda = hfma2(mb3, ca[3], pda);
            naa = hfma2(mb3, mb3, naa);
        }
        float x;
        x = hsum(cna); cn = x + __shfl_xor_sync(0xffffffffu, x, 1);
        x = hsum(pda); pd = x + __shfl_xor_sync(0xffffffffu, x, 1);
        x = hsum(naa); na = x + __shfl_xor_sync(0xffffffffu, x, 1);
    }

    if (h == 0) n1s[c] = fminf(rsqrtf(cn), 1e8f);   // 1/max(sqrt(cn),~0)
    __syncthreads();

    float obj = 0.f, pool = 0.f;
    if (h == 0) {
        float rpn = fminf(rsqrtf(pn), 1e8f);
        float ssum = 0.f, smax = -INFINITY;
#pragma unroll
        for (int k = 0; k < 9; ++k) {
            float s = dotf[k] * rpn * n1s[nb8[k] >> 3];
            if (pmask & (1u << k)) {
                ssum += s;
                smax = fmaxf(smax, s);
            }
        }
        if (p0c > THRS && pmask) obj = -5.0f * smax + ssum;
        float nb = fmaxf(p1c * sqrtf(cn), 1e-6f);
        float cosp = __fdividef(pd * p1c, fmaxf(sqrtf(na), 1e-6f) * nb);
        pool = -cosp * 0.5f * (p0c + p1c);
    }

    wl = wsum(wl); pool = wsum(pool); obj = wsum(obj);
    pres = wsum(pres); fsq = wsum(fsq); szp = wsum(szp); sfl = wsum(sfl);
    if ((tid & 31) == 0) {
        atomicAdd(&rd[0], (double)wl);
        atomicAdd(&rd[1], (double)pool);
        atomicAdd(&rd[2], (double)obj);
        atomicAdd(&rd[3], (double)pres);
        atomicAdd(&rd[4], (double)fsq);
        atomicAdd(&rd[5], (double)szp);
        atomicAdd(&rd[6], (double)sfl);
    }
    __syncthreads();
    if (tid == 0) {
#pragma unroll
        for (int q = 0; q < 7; ++q) atomicAdd(&g_slot[q][slot], rd[q]);
    }

    // ================= last-block finalize =================
    if (tid == 0) {
        __threadfence();
        unsigned old = atomicAdd(&g_ctr, 1u);
        isLast = (old == (unsigned)npair - 1u) ? 1u : 0u;
    }
    __syncthreads();

    if (isLast && tid == 0) {
        __threadfence();
        double acc[7];
#pragma unroll
        for (int q = 0; q < 7; ++q) {
            double s = 0.0;
#pragma unroll
            for (int r = 0; r < 16; ++r) { s += g_slot[q][r]; g_slot[q][r] = 0.0; }
            acc[q] = s;
        }
        g_ctr = 0u;

        int gi = *(const int*)gs;
        double gstep = (gi < 0 || gi > 1000000000) ? (double)__int_as_float(gi) : (double)gi;

        double scale_obj = gstep / 200000.0;        if (scale_obj > 1.0) scale_obj = 1.0;
        double scale_flow = 1.0 - gstep / 100000.0; if (scale_flow < 0.0) scale_flow = 0.0;

        double hinge = acc[5] - acc[6];
        if (hinge < 0.0) hinge = 0.0;
        double flow_loss = acc[4] + 100.0 * hinge;

        double loss = acc[0]                        // z_what_loss (ADJ_W=1)
                    + acc[3]                        // z_pres_loss (PRES_W=1)
                    + acc[1]                        // pool (POOL_W=1)
                    + acc[2] * scale_obj * 10.0     // objects * OBJ_W
                    + flow_loss * scale_flow;       // FLOW_W=1
        out[0] = (float)loss;
    }
}

extern "C" void kernel_launch(void* const* d_in, const int* in_sizes, int n_in,
                              void* d_out, int out_size) {
    const float* zw = (const float*)d_in[0];
    const float* zp = (const float*)d_in[1];
    const float* fl = (const float*)d_in[2];
    const void*  gs = d_in[3];
    int B = in_sizes[0] / (TT * GG * DD);

    static int configured = 0;
    if (!configured) {
        cudaFuncSetAttribute(fused_kernel, cudaFuncAttributeMaxDynamicSharedMemorySize, SMEM_BYTES);
        configured = 1;
    }

    int npair = (TT - 1) * B;
    fused_kernel<<<npair, 512, SMEM_BYTES>>>(zw, zp, fl, gs, (float*)d_out, B, npair);
}

// round 13
// speedup vs baseline: 1.4305x; 1.4305x over previous
#include <cuda_runtime.h>
#include <cuda_fp16.h>

#define TT 8
#define G  16
#define GG 256
#define DD 64
#define THRS 0.5f

// slot-spread accumulators: 0 wl, 1 pool, 2 obj, 3 pres, 4 flowsq, 5 sumzp, 6 sumflow
__device__ double g_slot[7][16];
__device__ unsigned g_ctr;

typedef unsigned long long u64;

__device__ __forceinline__ float wsum(float v) {
#pragma unroll
    for (int s = 16; s > 0; s >>= 1) v += __shfl_xor_sync(0xffffffffu, v, s);
    return v;
}

// ---- packed f32x2 helpers (exact wl path) ----
__device__ __forceinline__ u64 mkf(float lo, float hi) {
    u64 r; asm("mov.b64 %0, {%1, %2};" : "=l"(r) : "f"(lo), "f"(hi)); return r;
}
__device__ __forceinline__ u64 ffma2(u64 a, u64 b, u64 c) {
    u64 r; asm("fma.rn.f32x2 %0, %1, %2, %3;" : "=l"(r) : "l"(a), "l"(b), "l"(c)); return r;
}
__device__ __forceinline__ float lohisum(u64 v) {
    unsigned a, b; asm("mov.b64 {%0, %1}, %2;" : "=r"(a), "=r"(b) : "l"(v));
    return __uint_as_float(a) + __uint_as_float(b);
}

// ---- fp16x2 helpers ----
__device__ __forceinline__ unsigned pkh(float e0, float e1) {
    unsigned r;
    asm("cvt.rn.f16x2.f32 %0, %1, %2;" : "=r"(r) : "f"(e1), "f"(e0));
    return r;  // e0 lo half, e1 hi half
}
__device__ __forceinline__ unsigned hfma2(unsigned a, unsigned b, unsigned c) {
    unsigned r; asm("fma.rn.f16x2 %0, %1, %2, %3;" : "=r"(r) : "r"(a), "r"(b), "r"(c)); return r;
}
__device__ __forceinline__ unsigned hmul2(unsigned a, unsigned b) {
    unsigned r; asm("mul.rn.f16x2 %0, %1, %2;" : "=r"(r) : "r"(a), "r"(b)); return r;
}
__device__ __forceinline__ unsigned hmax2(unsigned a, unsigned b) {
    unsigned r; asm("max.f16x2 %0, %1, %2;" : "=r"(r) : "r"(a), "r"(b)); return r;
}
__device__ __forceinline__ float hsum(unsigned u) {
    float lo, hi;
    asm("{\n\t.reg .f16 a, b;\n\tmov.b32 {a, b}, %2;\n\tcvt.f32.f16 %0, a;\n\tcvt.f32.f16 %1, b;\n\t}"
        : "=f"(lo), "=f"(hi) : "r"(u));
    return lo + hi;
}

// swizzled uint4 index within a [GG][8]-uint4 frame (zero padding, conflict-free)
#define SWZ(cell, q) (((cell) << 3) + ((q) ^ ((cell) & 7)))

// s0 frame gets one extra all-zero row (cell index GG) for clamped pool rows
#define S0_ROWS (GG + 1)
#define SMEM_BYTES ((S0_ROWS * 8 + GG * 8) * 16 + 3 * GG * 4)  // 68,736 B -> 3 blocks/SM

// One block per (t,t+1,b) pair; thread = cell. Pres/flow terms folded in.
__global__ __launch_bounds__(256, 3) void fused_kernel(const float* __restrict__ zw,
                                                       const float* __restrict__ zp,
                                                       const float* __restrict__ fl,
                                                       const void* __restrict__ gs,
                                                       float* __restrict__ out,
                                                       int B, int npair) {
    extern __shared__ char smraw[];
    __shared__ double rd[7];
    __shared__ unsigned isLast;
    int tid = threadIdx.x;
    int blk = blockIdx.x;
    int slot = blk & 15;
    if (tid < 7) rd[tid] = 0.0;

    uint4* s0b = (uint4*)smraw;            // frame t fp16 [GG+1][8]; row GG = zeros
    uint4* s1b = s0b + S0_ROWS * 8;        // frame t+1 fp16 [GG][8]
    float* p0s = (float*)(s1b + GG * 8);
    float* p1s = p0s + GG;
    float* n1s = p1s + GG;                 // reciprocal norms of frame t+1 cells

    int b = blk % B, t = blk / B;
    size_t f0 = (size_t)(t * B + b);
    size_t f1 = f0 + B;
    const float4* g0 = (const float4*)(zw + f0 * (GG * DD));
    const float4* g1 = (const float4*)(zw + f1 * (GG * DD));

    p0s[tid] = zp[f0 * GG + tid];
    p1s[tid] = zp[f1 * GG + tid];
    if (tid < 32) ((unsigned*)(s0b + GG * 8))[tid] = 0u;   // zero row

    // coalesced load: exact fp32 z_what_loss (packed) + swizzled fp16 frames
    const u64 NEG1 = 0xBF800000BF800000ULL;
    u64 wl2 = 0ULL;
#pragma unroll
    for (int it = 0; it < 16; ++it) {
        int idx = it * 256 + tid;
        float4 a = g0[idx];
        float4 v = g1[idx];
        u64 d01 = ffma2(mkf(a.x, a.y), NEG1, mkf(v.x, v.y));
        u64 d23 = ffma2(mkf(a.z, a.w), NEG1, mkf(v.z, v.w));
        wl2 = ffma2(d01, d01, wl2);
        wl2 = ffma2(d23, d23, wl2);
        int cell = idx >> 4, d4 = idx & 15;
        int u2idx = SWZ(cell, d4 >> 1) * 2 + (d4 & 1);
        uint2 pa, pb;
        pa.x = pkh(a.x, a.y);  pa.y = pkh(a.z, a.w);
        pb.x = pkh(v.x, v.y);  pb.y = pkh(v.z, v.w);
        ((uint2*)s0b)[u2idx] = pa;
        ((uint2*)s1b)[u2idx] = pb;
    }
    float wl = lohisum(wl2);
    __syncthreads();

    int c = tid;
    int lane = tid & 31;
    int i = c >> 4, j = c & 15;
    int cb = c << 3, cx = c & 7;
    float p0c = p0s[c], p1c = p1s[c];
    unsigned z0h = pkh(p0c, p0c);

    // shuffle sources for column-direction (j +/- 1) within the 16-lane row group
    int lsrc = (lane & 16) | ((lane + 15) & 15);
    int rsrc = (lane & 16) | ((lane + 1) & 15);
    unsigned lm = (j == 0)  ? 0u : 0xFFFFFFFFu;   // zero the wrapped value at edges
    unsigned rm = (j == 15) ? 0u : 0xFFFFFFFFu;   // (values >= 0 so max-with-0 is identity)

    // ---- folded pres/flow terms for image t (and image 7 when t == TT-2) ----
    float fsq = 0.f, szp = 0.f, sfl = 0.f, pres = 0.f;
    {
        float f = fl[f0 * GG + c];
        float mx = -INFINITY;
#pragma unroll
        for (int di = -1; di <= 1; ++di) {
            int ii = i + di;
            if (ii < 0 || ii >= G) continue;
#pragma unroll
            for (int dj = -1; dj <= 1; ++dj) {
                int jj = j + dj;
                if (jj < 0 || jj >= G) continue;
                mx = fmaxf(mx, p0s[ii * G + jj]);
            }
        }
        fsq = (f > 0.5f) ? (mx - f) * (mx - f) : 0.f;
        szp = p0c;
        sfl = f;
        if (t >= 1) {   // pres triple centered at t
            float za = zp[(f0 - B) * GG + c];
            float zb = p1c;
            float dba = zb - za;
            float sim = 1.f - dba * dba;
            float d1 = zb - p0c, d2 = za - p0c;
            pres = sim * (d1 * d1 + d2 * d2);
        }
        if (t == TT - 2) {   // last pair block also handles image TT-1
            float f7 = fl[f1 * GG + c];
            float mx7 = -INFINITY;
#pragma unroll
            for (int di = -1; di <= 1; ++di) {
                int ii = i + di;
                if (ii < 0 || ii >= G) continue;
#pragma unroll
                for (int dj = -1; dj <= 1; ++dj) {
                    int jj = j + dj;
                    if (jj < 0 || jj >= G) continue;
                    mx7 = fmaxf(mx7, p1s[ii * G + jj]);
                }
            }
            fsq += (f7 > 0.5f) ? (mx7 - f7) * (mx7 - f7) : 0.f;
            szp += p1c;
            sfl += f7;
        }
    }

    // wrapped neighbor indexing (objects term, frame t+1) + pres mask
    int nb8[9];
    unsigned pmask = 0;
    {
        int k = 0;
#pragma unroll
        for (int di = -1; di <= 1; ++di)
#pragma unroll
            for (int dj = -1; dj <= 1; ++dj, ++k) {
                int nc = ((i + di) & 15) * 16 + ((j + dj) & 15);
                nb8[k] = nc << 3;
                if (p1s[nc] > THRS) pmask |= (1u << k);
            }
    }

    // ---- loop A: prior norm + 9 wrapped dots + in-place COLUMN-MAX transform ----
    // after this loop, s0b[c][q] holds max over j' in {j-1,j,j+1} of |s0|*p0 (fp16)
    unsigned dacc[9] = {0u, 0u, 0u, 0u, 0u, 0u, 0u, 0u, 0u};
    unsigned pna = 0u, pnb = 0u;
#pragma unroll
    for (int q = 0; q < 8; ++q) {
        int off = q ^ cx;
        uint4 pu = s0b[cb + off];
        const unsigned* pw = (const unsigned*)&pu;
        pna = hfma2(pw[0], pw[0], pna);
        pnb = hfma2(pw[1], pw[1], pnb);
        pna = hfma2(pw[2], pw[2], pna);
        pnb = hfma2(pw[3], pw[3], pnb);
#pragma unroll
        for (int k = 0; k < 9; ++k) {
            uint4 nu = s1b[nb8[k] + (q ^ ((nb8[k] >> 3) & 7))];
            const unsigned* nw = (const unsigned*)&nu;
            unsigned d = dacc[k];
            d = hfma2(pw[0], nw[0], d);
            d = hfma2(pw[1], nw[1], d);
            d = hfma2(pw[2], nw[2], d);
            d = hfma2(pw[3], nw[3], d);
            dacc[k] = d;
        }
        uint4 tw;
        unsigned* twp = (unsigned*)&tw;
        twp[0] = hmul2(pw[0] & 0x7FFF7FFFu, z0h);
        twp[1] = hmul2(pw[1] & 0x7FFF7FFFu, z0h);
        twp[2] = hmul2(pw[2] & 0x7FFF7FFFu, z0h);
        twp[3] = hmul2(pw[3] & 0x7FFF7FFFu, z0h);
        uint4 cm;
        unsigned* cmp = (unsigned*)&cm;
#pragma unroll
        for (int w = 0; w < 4; ++w) {
            unsigned lv = __shfl_sync(0xffffffffu, twp[w], lsrc) & lm;
            unsigned rv = __shfl_sync(0xffffffffu, twp[w], rsrc) & rm;
            cmp[w] = hmax2(hmax2(lv, twp[w]), rv);
        }
        s0b[cb + off] = cm;
    }
    float pn = hsum(pna) + hsum(pnb);
    float dotf[9];
#pragma unroll
    for (int k = 0; k < 9; ++k) dotf[k] = hsum(dacc[k]);
    __syncthreads();   // all rows hold column-max now

    // clamped row indices for the pool: out-of-grid -> zero row (cell GG)
    int rup = ((i > 0)  ? c - 16 : GG) << 3;
    int rdn = ((i < 15) ? c + 16 : GG) << 3;
    int rux = (rup >> 3) & 7, rdx = (rdn >> 3) & 7;

    // ---- loop B: row-max of column-max (3 LDS/q) + pool partials (fp16x2) ----
    unsigned cna = 0u, pda = 0u, naa = 0u;
#pragma unroll
    for (int q = 0; q < 8; ++q) {
        uint4 cu = s1b[cb + (q ^ cx)];
        const unsigned* cw = (const unsigned*)&cu;
        uint4 su = s0b[rup + (q ^ rux)];
        uint4 sc = s0b[cb + (q ^ cx)];
        uint4 sd = s0b[rdn + (q ^ rdx)];
        const unsigned* uu = (const unsigned*)&su;
        const unsigned* ucn = (const unsigned*)&sc;
        const unsigned* ud = (const unsigned*)&sd;
#pragma unroll
        for (int w = 0; w < 4; ++w) {
            unsigned ca = cw[w] & 0x7FFF7FFFu;
            cna = hfma2(ca, ca, cna);
            unsigned mb = hmax2(hmax2(uu[w], ucn[w]), ud[w]);
            pda = hfma2(mb, ca, pda);
            naa = hfma2(mb, mb, naa);
        }
    }
    float cn = hsum(cna), pd = hsum(pda), na = hsum(naa);

    n1s[c] = fminf(rsqrtf(cn), 1e8f);    // 1/max(sqrt(cn),~0)
    __syncthreads();

    float rpn = fminf(rsqrtf(pn), 1e8f);
    float ssum = 0.f, smax = -INFINITY;
#pragma unroll
    for (int k = 0; k < 9; ++k) {
        float s = dotf[k] * rpn * n1s[nb8[k] >> 3];
        if (pmask & (1u << k)) {
            ssum += s;
            smax = fmaxf(smax, s);
        }
    }
    float obj = (p0c > THRS && pmask) ? (-5.0f * smax + ssum) : 0.f;
    float nb = fmaxf(p1c * sqrtf(cn), 1e-6f);
    float cosp = __fdividef(pd * p1c, fmaxf(sqrtf(na), 1e-6f) * nb);
    float pool = -cosp * 0.5f * (p0c + p1c);

    wl = wsum(wl); pool = wsum(pool); obj = wsum(obj);
    pres = wsum(pres); fsq = wsum(fsq); szp = wsum(szp); sfl = wsum(sfl);
    if ((tid & 31) == 0) {
        atomicAdd(&rd[0], (double)wl);
        atomicAdd(&rd[1], (double)pool);
        atomicAdd(&rd[2], (double)obj);
        atomicAdd(&rd[3], (double)pres);
        atomicAdd(&rd[4], (double)fsq);
        atomicAdd(&rd[5], (double)szp);
        atomicAdd(&rd[6], (double)sfl);
    }
    __syncthreads();
    if (tid == 0) {
#pragma unroll
        for (int q = 0; q < 7; ++q) atomicAdd(&g_slot[q][slot], rd[q]);
    }

    // ================= last-block finalize =================
    if (tid == 0) {
        __threadfence();
        unsigned old = atomicAdd(&g_ctr, 1u);
        isLast = (old == (unsigned)npair - 1u) ? 1u : 0u;
    }
    __syncthreads();

    if (isLast && tid == 0) {
        __threadfence();
        double acc[7];
#pragma unroll
        for (int q = 0; q < 7; ++q) {
            double s = 0.0;
#pragma unroll
            for (int r = 0; r < 16; ++r) { s += g_slot[q][r]; g_slot[q][r] = 0.0; }
            acc[q] = s;
        }
        g_ctr = 0u;

        int gi = *(const int*)gs;
        double gstep = (gi < 0 || gi > 1000000000) ? (double)__int_as_float(gi) : (double)gi;

        double scale_obj = gstep / 200000.0;        if (scale_obj > 1.0) scale_obj = 1.0;
        double scale_flow = 1.0 - gstep / 100000.0; if (scale_flow < 0.0) scale_flow = 0.0;

        double hinge = acc[5] - acc[6];
        if (hinge < 0.0) hinge = 0.0;
        double flow_loss = acc[4] + 100.0 * hinge;

        double loss = acc[0]                        // z_what_loss (ADJ_W=1)
                    + acc[3]                        // z_pres_loss (PRES_W=1)
                    + acc[1]                        // pool (POOL_W=1)
                    + acc[2] * scale_obj * 10.0     // objects * OBJ_W
                    + flow_loss * scale_flow;       // FLOW_W=1
        out[0] = (float)loss;
    }
}

extern "C" void kernel_launch(void* const* d_in, const int* in_sizes, int n_in,
                              void* d_out, int out_size) {
    const float* zw = (const float*)d_in[0];
    const float* zp = (const float*)d_in[1];
    const float* fl = (const float*)d_in[2];
    const void*  gs = d_in[3];
    int B = in_sizes[0] / (TT * GG * DD);

    static int configured = 0;
    if (!configured) {
        cudaFuncSetAttribute(fused_kernel, cudaFuncAttributeMaxDynamicSharedMemorySize, SMEM_BYTES);
        configured = 1;
    }

    int npair = (TT - 1) * B;
    fused_kernel<<<npair, 256, SMEM_BYTES>>>(zw, zp, fl, gs, (float*)d_out, B, npair);
}

// round 14
// speedup vs baseline: 1.4919x; 1.0430x over previous
#include <cuda_runtime.h>
#include <cuda_fp16.h>

#define TT 8
#define G  16
#define GG 256
#define DD 64
#define THRS 0.5f

// slot-spread accumulators: 0 wl, 1 pool, 2 obj, 3 pres, 4 flowsq, 5 sumzp, 6 sumflow
__device__ double g_slot[7][16];
__device__ unsigned g_ctr;

typedef unsigned long long u64;

__device__ __forceinline__ float wsum(float v) {
#pragma unroll
    for (int s = 16; s > 0; s >>= 1) v += __shfl_xor_sync(0xffffffffu, v, s);
    return v;
}

// ---- packed f32x2 helpers (exact wl path) ----
__device__ __forceinline__ u64 mkf(float lo, float hi) {
    u64 r; asm("mov.b64 %0, {%1, %2};" : "=l"(r) : "f"(lo), "f"(hi)); return r;
}
__device__ __forceinline__ u64 ffma2(u64 a, u64 b, u64 c) {
    u64 r; asm("fma.rn.f32x2 %0, %1, %2, %3;" : "=l"(r) : "l"(a), "l"(b), "l"(c)); return r;
}
__device__ __forceinline__ float lohisum(u64 v) {
    unsigned a, b; asm("mov.b64 {%0, %1}, %2;" : "=r"(a), "=r"(b) : "l"(v));
    return __uint_as_float(a) + __uint_as_float(b);
}

// ---- fp16x2 helpers ----
__device__ __forceinline__ unsigned pkh(float e0, float e1) {
    unsigned r;
    asm("cvt.rn.f16x2.f32 %0, %1, %2;" : "=r"(r) : "f"(e1), "f"(e0));
    return r;  // e0 lo half, e1 hi half
}
__device__ __forceinline__ unsigned hfma2(unsigned a, unsigned b, unsigned c) {
    unsigned r; asm("fma.rn.f16x2 %0, %1, %2, %3;" : "=r"(r) : "r"(a), "r"(b), "r"(c)); return r;
}
__device__ __forceinline__ unsigned hmul2(unsigned a, unsigned b) {
    unsigned r; asm("mul.rn.f16x2 %0, %1, %2;" : "=r"(r) : "r"(a), "r"(b)); return r;
}
__device__ __forceinline__ unsigned hsub2(unsigned a, unsigned b) {
    unsigned r; asm("sub.rn.f16x2 %0, %1, %2;" : "=r"(r) : "r"(a), "r"(b)); return r;
}
__device__ __forceinline__ unsigned hmax2(unsigned a, unsigned b) {
    unsigned r; asm("max.f16x2 %0, %1, %2;" : "=r"(r) : "r"(a), "r"(b)); return r;
}
__device__ __forceinline__ float hsum(unsigned u) {
    float lo, hi;
    asm("{\n\t.reg .f16 a, b;\n\tmov.b32 {a, b}, %2;\n\tcvt.f32.f16 %0, a;\n\tcvt.f32.f16 %1, b;\n\t}"
        : "=f"(lo), "=f"(hi) : "r"(u));
    return lo + hi;
}
__device__ __forceinline__ float sq2acc(unsigned d, float acc) {
    float lo, hi;
    asm("{\n\t.reg .f16 a, b;\n\tmov.b32 {a, b}, %2;\n\tcvt.f32.f16 %0, a;\n\tcvt.f32.f16 %1, b;\n\t}"
        : "=f"(lo), "=f"(hi) : "r"(d));
    return fmaf(lo, lo, fmaf(hi, hi, acc));
}

// swizzled uint4 index within a [GG][8]-uint4 frame (zero padding, conflict-free)
#define SWZ(cell, q) (((cell) << 3) + ((q) ^ ((cell) & 7)))

// each frame buffer has one extra all-zero row (cell index GG) for clamped pool rows
#define S0_ROWS (GG + 1)
#define SMEM_BYTES (2 * S0_ROWS * 8 * 16 + 3 * GG * 4)  // 68,864 B -> 3 blocks/SM

// Processes one temporal pair. s0 frame is DESTROYED (replaced by column-max of
// |s0|*p0). Folds pres/flow terms for image t (and image t+1 when t == TT-2).
__device__ __forceinline__ void process_pair(
    uint4* __restrict__ s0b, uint4* __restrict__ s1b,
    const float* __restrict__ p0s, const float* __restrict__ p1s, float* __restrict__ n1s,
    const float* __restrict__ zp, const float* __restrict__ fl,
    int B, int t, size_t f0, int tid,
    float& pool_a, float& obj_a, float& pres_a, float& fsq_a, float& szp_a, float& sfl_a) {

    int c = tid;
    int lane = tid & 31;
    int i = c >> 4, j = c & 15;
    int cb = c << 3, cx = c & 7;
    float p0c = p0s[c], p1c = p1s[c];
    unsigned z0h = pkh(p0c, p0c);

    int lsrc = (lane & 16) | ((lane + 15) & 15);
    int rsrc = (lane & 16) | ((lane + 1) & 15);
    unsigned lm = (j == 0)  ? 0u : 0xFFFFFFFFu;
    unsigned rm = (j == 15) ? 0u : 0xFFFFFFFFu;

    // ---- folded pres/flow terms for image t (and image t+1 if t == TT-2) ----
    {
        float f = fl[f0 * GG + c];
        float mx = -INFINITY;
#pragma unroll
        for (int di = -1; di <= 1; ++di) {
            int ii = i + di;
            if (ii < 0 || ii >= G) continue;
#pragma unroll
            for (int dj = -1; dj <= 1; ++dj) {
                int jj = j + dj;
                if (jj < 0 || jj >= G) continue;
                mx = fmaxf(mx, p0s[ii * G + jj]);
            }
        }
        fsq_a += (f > 0.5f) ? (mx - f) * (mx - f) : 0.f;
        szp_a += p0c;
        sfl_a += f;
        if (t >= 1) {   // pres triple centered at t
            float za = zp[(f0 - B) * GG + c];
            float zb = p1c;
            float dba = zb - za;
            float sim = 1.f - dba * dba;
            float d1 = zb - p0c, d2 = za - p0c;
            pres_a += sim * (d1 * d1 + d2 * d2);
        }
        if (t == TT - 2) {   // also handle the final image
            float f7 = fl[(f0 + B) * GG + c];
            float mx7 = -INFINITY;
#pragma unroll
            for (int di = -1; di <= 1; ++di) {
                int ii = i + di;
                if (ii < 0 || ii >= G) continue;
#pragma unroll
                for (int dj = -1; dj <= 1; ++dj) {
                    int jj = j + dj;
                    if (jj < 0 || jj >= G) continue;
                    mx7 = fmaxf(mx7, p1s[ii * G + jj]);
                }
            }
            fsq_a += (f7 > 0.5f) ? (mx7 - f7) * (mx7 - f7) : 0.f;
            szp_a += p1c;
            sfl_a += f7;
        }
    }

    // wrapped neighbor indexing (objects term, frame t+1) + pres mask
    int nb8[9];
    unsigned pmask = 0;
    {
        int k = 0;
#pragma unroll
        for (int di = -1; di <= 1; ++di)
#pragma unroll
            for (int dj = -1; dj <= 1; ++dj, ++k) {
                int nc = ((i + di) & 15) * 16 + ((j + dj) & 15);
                nb8[k] = nc << 3;
                if (p1s[nc] > THRS) pmask |= (1u << k);
            }
    }

    // ---- loop A: prior norm + 9 wrapped dots + in-place COLUMN-MAX transform ----
    unsigned dacc[9] = {0u, 0u, 0u, 0u, 0u, 0u, 0u, 0u, 0u};
    unsigned pna = 0u, pnb = 0u;
#pragma unroll
    for (int q = 0; q < 8; ++q) {
        int off = q ^ cx;
        uint4 pu = s0b[cb + off];
        const unsigned* pw = (const unsigned*)&pu;
        pna = hfma2(pw[0], pw[0], pna);
        pnb = hfma2(pw[1], pw[1], pnb);
        pna = hfma2(pw[2], pw[2], pna);
        pnb = hfma2(pw[3], pw[3], pnb);
#pragma unroll
        for (int k = 0; k < 9; ++k) {
            uint4 nu = s1b[nb8[k] + (q ^ ((nb8[k] >> 3) & 7))];
            const unsigned* nw = (const unsigned*)&nu;
            unsigned d = dacc[k];
            d = hfma2(pw[0], nw[0], d);
            d = hfma2(pw[1], nw[1], d);
            d = hfma2(pw[2], nw[2], d);
            d = hfma2(pw[3], nw[3], d);
            dacc[k] = d;
        }
        uint4 tw;
        unsigned* twp = (unsigned*)&tw;
        twp[0] = hmul2(pw[0] & 0x7FFF7FFFu, z0h);
        twp[1] = hmul2(pw[1] & 0x7FFF7FFFu, z0h);
        twp[2] = hmul2(pw[2] & 0x7FFF7FFFu, z0h);
        twp[3] = hmul2(pw[3] & 0x7FFF7FFFu, z0h);
        uint4 cm;
        unsigned* cmp = (unsigned*)&cm;
#pragma unroll
        for (int w = 0; w < 4; ++w) {
            unsigned lv = __shfl_sync(0xffffffffu, twp[w], lsrc) & lm;
            unsigned rv = __shfl_sync(0xffffffffu, twp[w], rsrc) & rm;
            cmp[w] = hmax2(hmax2(lv, twp[w]), rv);
        }
        s0b[cb + off] = cm;
    }
    float pn = hsum(pna) + hsum(pnb);
    float dotf[9];
#pragma unroll
    for (int k = 0; k < 9; ++k) dotf[k] = hsum(dacc[k]);
    __syncthreads();   // all rows hold column-max now

    // clamped row indices for the pool: out-of-grid -> zero row (cell GG)
    int rup = ((i > 0)  ? c - 16 : GG) << 3;
    int rdn = ((i < 15) ? c + 16 : GG) << 3;
    int rux = (rup >> 3) & 7, rdx = (rdn >> 3) & 7;

    // ---- loop B: row-max of column-max (3 LDS/q) + pool partials (fp16x2) ----
    unsigned cna = 0u, pda = 0u, naa = 0u;
#pragma unroll
    for (int q = 0; q < 8; ++q) {
        uint4 cu = s1b[cb + (q ^ cx)];
        const unsigned* cw = (const unsigned*)&cu;
        uint4 su = s0b[rup + (q ^ rux)];
        uint4 sc = s0b[cb + (q ^ cx)];
        uint4 sd = s0b[rdn + (q ^ rdx)];
        const unsigned* uu = (const unsigned*)&su;
        const unsigned* ucn = (const unsigned*)&sc;
        const unsigned* ud = (const unsigned*)&sd;
#pragma unroll
        for (int w = 0; w < 4; ++w) {
            unsigned ca = cw[w] & 0x7FFF7FFFu;
            cna = hfma2(ca, ca, cna);
            unsigned mb = hmax2(hmax2(uu[w], ucn[w]), ud[w]);
            pda = hfma2(mb, ca, pda);
            naa = hfma2(mb, mb, naa);
        }
    }
    float cn = hsum(cna), pd = hsum(pda), na = hsum(naa);

    n1s[c] = fminf(rsqrtf(cn), 1e8f);    // 1/max(sqrt(cn),~0)
    __syncthreads();

    float rpn = fminf(rsqrtf(pn), 1e8f);
    float ssum = 0.f, smax = -INFINITY;
#pragma unroll
    for (int k = 0; k < 9; ++k) {
        float s = dotf[k] * rpn * n1s[nb8[k] >> 3];
        if (pmask & (1u << k)) {
            ssum += s;
            smax = fmaxf(smax, s);
        }
    }
    if (p0c > THRS && pmask) obj_a += -5.0f * smax + ssum;
    float nb = fmaxf(p1c * sqrtf(cn), 1e-6f);
    float cosp = __fdividef(pd * p1c, fmaxf(sqrtf(na), 1e-6f) * nb);
    pool_a += -cosp * 0.5f * (p0c + p1c);
}

// Heavy blocks [0, 3B): pairs (2g, 2g+1) of batch b, 3 frame loads for 2 pairs.
// Light blocks [3B, 4B): pair t=6 (+ image 7 folding). Last block finalizes.
__global__ __launch_bounds__(256, 3) void fused_kernel(const float* __restrict__ zw,
                                                       const float* __restrict__ zp,
                                                       const float* __restrict__ fl,
                                                       const void* __restrict__ gs,
                                                       float* __restrict__ out,
                                                       int B) {
    extern __shared__ char smraw[];
    __shared__ double rd[7];
    __shared__ unsigned isLast;
    int tid = threadIdx.x;
    int blk = blockIdx.x;
    int slot = blk & 15;
    if (tid < 7) rd[tid] = 0.0;

    uint4* bufA = (uint4*)smraw;            // [GG+1][8] fp16 frame; row GG = zeros
    uint4* bufB = bufA + S0_ROWS * 8;
    float* pA = (float*)(bufB + S0_ROWS * 8);
    float* pB = pA + GG;
    float* n1s = pB + GG;

    int nheavy = 3 * B;
    bool heavy = blk < nheavy;
    int b = heavy ? (blk % B) : (blk - nheavy);
    int t0 = heavy ? 2 * (blk / B) : (TT - 2);
    size_t f0 = (size_t)(t0 * B + b);

    // zero rows of both buffers
    if (tid < 32) ((unsigned*)(bufA + GG * 8))[tid] = 0u;
    else if (tid < 64) ((unsigned*)(bufB + GG * 8))[tid - 32] = 0u;
    pA[tid] = zp[f0 * GG + tid];
    pB[tid] = zp[(f0 + B) * GG + tid];

    // ---- load phase 1: frames t0, t0+1 (exact fp32 wl) ----
    const float4* g0 = (const float4*)(zw + f0 * (GG * DD));
    const float4* g1 = (const float4*)(zw + (f0 + B) * (GG * DD));
    const u64 NEG1 = 0xBF800000BF800000ULL;
    u64 wl2 = 0ULL;
#pragma unroll
    for (int it = 0; it < 16; ++it) {
        int idx = it * 256 + tid;
        float4 a = g0[idx];
        float4 v = g1[idx];
        u64 d01 = ffma2(mkf(a.x, a.y), NEG1, mkf(v.x, v.y));
        u64 d23 = ffma2(mkf(a.z, a.w), NEG1, mkf(v.z, v.w));
        wl2 = ffma2(d01, d01, wl2);
        wl2 = ffma2(d23, d23, wl2);
        int cell = idx >> 4, d4 = idx & 15;
        int u2idx = SWZ(cell, d4 >> 1) * 2 + (d4 & 1);
        uint2 pa, pb;
        pa.x = pkh(a.x, a.y);  pa.y = pkh(a.z, a.w);
        pb.x = pkh(v.x, v.y);  pb.y = pkh(v.z, v.w);
        ((uint2*)bufA)[u2idx] = pa;
        ((uint2*)bufB)[u2idx] = pb;
    }
    float wl = lohisum(wl2);
    __syncthreads();

    float pool_a = 0.f, obj_a = 0.f, pres_a = 0.f, fsq_a = 0.f, szp_a = 0.f, sfl_a = 0.f;

    // ---- pair 1: (t0, t0+1) ----
    process_pair(bufA, bufB, pA, pB, n1s, zp, fl, B, t0, f0, tid,
                 pool_a, obj_a, pres_a, fsq_a, szp_a, sfl_a);

    if (heavy) {
        __syncthreads();   // protect bufA / n1s before reuse

        // ---- load phase 2: frame t0+2 into bufA; wl vs fp16 bufB ----
        const float4* g2 = (const float4*)(zw + (f0 + 2 * B) * (GG * DD));
        float wlh = 0.f;
#pragma unroll
        for (int it = 0; it < 16; ++it) {
            int idx = it * 256 + tid;
            float4 cc = g2[idx];
            unsigned c01 = pkh(cc.x, cc.y), c23 = pkh(cc.z, cc.w);
            int cell = idx >> 4, d4 = idx & 15;
            int u2idx = SWZ(cell, d4 >> 1) * 2 + (d4 & 1);
            uint2 bv = ((const uint2*)bufB)[u2idx];
            wlh = sq2acc(hsub2(c01, bv.x), wlh);
            wlh = sq2acc(hsub2(c23, bv.y), wlh);
            ((uint2*)bufA)[u2idx] = make_uint2(c01, c23);
        }
        wl += wlh;
        pA[tid] = zp[(f0 + 2 * B) * GG + tid];   // pair 2: p0 = pB, p1 = pA
        __syncthreads();

        // ---- pair 2: (t0+1, t0+2); roles swapped ----
        process_pair(bufB, bufA, pB, pA, n1s, zp, fl, B, t0 + 1, f0 + B, tid,
                     pool_a, obj_a, pres_a, fsq_a, szp_a, sfl_a);
    }

    // ---- accumulation ----
    wl = wsum(wl); pool_a = wsum(pool_a); obj_a = wsum(obj_a);
    pres_a = wsum(pres_a); fsq_a = wsum(fsq_a); szp_a = wsum(szp_a); sfl_a = wsum(sfl_a);
    if ((tid & 31) == 0) {
        atomicAdd(&rd[0], (double)wl);
        atomicAdd(&rd[1], (double)pool_a);
        atomicAdd(&rd[2], (double)obj_a);
        atomicAdd(&rd[3], (double)pres_a);
        atomicAdd(&rd[4], (double)fsq_a);
        atomicAdd(&rd[5], (double)szp_a);
        atomicAdd(&rd[6], (double)sfl_a);
    }
    __syncthreads();
    if (tid == 0) {
#pragma unroll
        for (int q = 0; q < 7; ++q) atomicAdd(&g_slot[q][slot], rd[q]);
    }

    // ================= last-block finalize =================
    if (tid == 0) {
        __threadfence();
        unsigned old = atomicAdd(&g_ctr, 1u);
        isLast = (old == gridDim.x - 1u) ? 1u : 0u;
    }
    __syncthreads();

    if (isLast && tid == 0) {
        __threadfence();
        double acc[7];
#pragma unroll
        for (int q = 0; q < 7; ++q) {
            double s = 0.0;
#pragma unroll
            for (int r = 0; r < 16; ++r) { s += g_slot[q][r]; g_slot[q][r] = 0.0; }
            acc[q] = s;
        }
        g_ctr = 0u;

        int gi = *(const int*)gs;
        double gstep = (gi < 0 || gi > 1000000000) ? (double)__int_as_float(gi) : (double)gi;

        double scale_obj = gstep / 200000.0;        if (scale_obj > 1.0) scale_obj = 1.0;
        double scale_flow = 1.0 - gstep / 100000.0; if (scale_flow < 0.0) scale_flow = 0.0;

        double hinge = acc[5] - acc[6];
        if (hinge < 0.0) hinge = 0.0;
        double flow_loss = acc[4] + 100.0 * hinge;

        double loss = acc[0]                        // z_what_loss (ADJ_W=1)
                    + acc[3]                        // z_pres_loss (PRES_W=1)
                    + acc[1]                        // pool (POOL_W=1)
                    + acc[2] * scale_obj * 10.0     // objects * OBJ_W
                    + flow_loss * scale_flow;       // FLOW_W=1
        out[0] = (float)loss;
    }
}

extern "C" void kernel_launch(void* const* d_in, const int* in_sizes, int n_in,
                              void* d_out, int out_size) {
    const float* zw = (const float*)d_in[0];
    const float* zp = (const float*)d_in[1];
    const float* fl = (const float*)d_in[2];
    const void*  gs = d_in[3];
    int B = in_sizes[0] / (TT * GG * DD);

    static int configured = 0;
    if (!configured) {
        cudaFuncSetAttribute(fused_kernel, cudaFuncAttributeMaxDynamicSharedMemorySize, SMEM_BYTES);
        configured = 1;
    }

    fused_kernel<<<4 * B, 256, SMEM_BYTES>>>(zw, zp, fl, gs, (float*)d_out, B);
}

// round 15
// speedup vs baseline: 1.6658x; 1.1165x over previous
#include <cuda_runtime.h>
#include <cuda_fp16.h>

#define TT 8
#define G  16
#define GG 256
#define DD 64
#define THRS 0.5f

// slot-spread accumulators: 0 wl, 1 pool, 2 obj, 3 pres, 4 flowsq, 5 sumzp, 6 sumflow
__device__ double g_slot[7][16];
__device__ unsigned g_ctr;

typedef unsigned long long u64;

__device__ __forceinline__ float wsum(float v) {
#pragma unroll
    for (int s = 16; s > 0; s >>= 1) v += __shfl_xor_sync(0xffffffffu, v, s);
    return v;
}

// ---- packed f32x2 helpers (exact wl path) ----
__device__ __forceinline__ u64 mkf(float lo, float hi) {
    u64 r; asm("mov.b64 %0, {%1, %2};" : "=l"(r) : "f"(lo), "f"(hi)); return r;
}
__device__ __forceinline__ u64 ffma2(u64 a, u64 b, u64 c) {
    u64 r; asm("fma.rn.f32x2 %0, %1, %2, %3;" : "=l"(r) : "l"(a), "l"(b), "l"(c)); return r;
}
__device__ __forceinline__ float lohisum(u64 v) {
    unsigned a, b; asm("mov.b64 {%0, %1}, %2;" : "=r"(a), "=r"(b) : "l"(v));
    return __uint_as_float(a) + __uint_as_float(b);
}

// ---- fp16x2 helpers ----
__device__ __forceinline__ unsigned pkh(float e0, float e1) {
    unsigned r;
    asm("cvt.rn.f16x2.f32 %0, %1, %2;" : "=r"(r) : "f"(e1), "f"(e0));
    return r;  // e0 lo half, e1 hi half
}
__device__ __forceinline__ unsigned hfma2(unsigned a, unsigned b, unsigned c) {
    unsigned r; asm("fma.rn.f16x2 %0, %1, %2, %3;" : "=r"(r) : "r"(a), "r"(b), "r"(c)); return r;
}
__device__ __forceinline__ unsigned hmul2(unsigned a, unsigned b) {
    unsigned r; asm("mul.rn.f16x2 %0, %1, %2;" : "=r"(r) : "r"(a), "r"(b)); return r;
}
__device__ __forceinline__ unsigned hsub2(unsigned a, unsigned b) {
    unsigned r; asm("sub.rn.f16x2 %0, %1, %2;" : "=r"(r) : "r"(a), "r"(b)); return r;
}
__device__ __forceinline__ unsigned hmax2(unsigned a, unsigned b) {
    unsigned r; asm("max.f16x2 %0, %1, %2;" : "=r"(r) : "r"(a), "r"(b)); return r;
}
__device__ __forceinline__ float hsum(unsigned u) {
    float lo, hi;
    asm("{\n\t.reg .f16 a, b;\n\tmov.b32 {a, b}, %2;\n\tcvt.f32.f16 %0, a;\n\tcvt.f32.f16 %1, b;\n\t}"
        : "=f"(lo), "=f"(hi) : "r"(u));
    return lo + hi;
}
__device__ __forceinline__ float sq2acc(unsigned d, float acc) {
    float lo, hi;
    asm("{\n\t.reg .f16 a, b;\n\tmov.b32 {a, b}, %2;\n\tcvt.f32.f16 %0, a;\n\tcvt.f32.f16 %1, b;\n\t}"
        : "=f"(lo), "=f"(hi) : "r"(d));
    return fmaf(lo, lo, fmaf(hi, hi, acc));
}

// swizzled uint4 index within a [GG][8]-uint4 frame (zero padding, conflict-free)
#define SWZ(cell, q) (((cell) << 3) + ((q) ^ ((cell) & 7)))

#define S0_ROWS (GG + 1)          // +1 zero row for clamped pool rows
#define D_STRIDE 26               // u32 stride of a D row (52 fp16; conflict-free)
#define SMEM_BYTES (2 * S0_ROWS * 8 * 16 + 64 * D_STRIDE * 4 + 3 * GG * 4)  // 75,520 B

// Processes one temporal pair. s0 frame is DESTROYED (replaced by column-max of
// |s0|*p0). Dots computed on tensor cores (mma.sync m16n8k16, f32 accum).
__device__ __forceinline__ void process_pair(
    uint4* __restrict__ s0b, uint4* __restrict__ s1b, unsigned* __restrict__ Dsm,
    const float* __restrict__ p0s, const float* __restrict__ p1s, float* __restrict__ n1s,
    const float* __restrict__ zp, const float* __restrict__ fl,
    int B, int t, size_t f0, int tid,
    float& pool_a, float& obj_a, float& pres_a, float& fsq_a, float& szp_a, float& sfl_a) {

    int c = tid;
    int lane = tid & 31;
    int wid = tid >> 5;
    int i = c >> 4, j = c & 15;
    int cb = c << 3, cx = c & 7;
    float p0c = p0s[c], p1c = p1s[c];
    unsigned z0h = pkh(p0c, p0c);

    int lsrc = (lane & 16) | ((lane + 15) & 15);
    int rsrc = (lane & 16) | ((lane + 1) & 15);
    unsigned lmsk = (j == 0)  ? 0u : 0xFFFFFFFFu;
    unsigned rmsk = (j == 15) ? 0u : 0xFFFFFFFFu;

    // ---- folded pres/flow terms for image t (and image t+1 if t == TT-2) ----
    {
        float f = fl[f0 * GG + c];
        float mx = -INFINITY;
#pragma unroll
        for (int di = -1; di <= 1; ++di) {
            int ii = i + di;
            if (ii < 0 || ii >= G) continue;
#pragma unroll
            for (int dj = -1; dj <= 1; ++dj) {
                int jj = j + dj;
                if (jj < 0 || jj >= G) continue;
                mx = fmaxf(mx, p0s[ii * G + jj]);
            }
        }
        fsq_a += (f > 0.5f) ? (mx - f) * (mx - f) : 0.f;
        szp_a += p0c;
        sfl_a += f;
        if (t >= 1) {
            float za = zp[(f0 - B) * GG + c];
            float zb = p1c;
            float dba = zb - za;
            float sim = 1.f - dba * dba;
            float d1 = zb - p0c, d2 = za - p0c;
            pres_a += sim * (d1 * d1 + d2 * d2);
        }
        if (t == TT - 2) {
            float f7 = fl[(f0 + B) * GG + c];
            float mx7 = -INFINITY;
#pragma unroll
            for (int di = -1; di <= 1; ++di) {
                int ii = i + di;
                if (ii < 0 || ii >= G) continue;
#pragma unroll
                for (int dj = -1; dj <= 1; ++dj) {
                    int jj = j + dj;
                    if (jj < 0 || jj >= G) continue;
                    mx7 = fmaxf(mx7, p1s[ii * G + jj]);
                }
            }
            fsq_a += (f7 > 0.5f) ? (mx7 - f7) * (mx7 - f7) : 0.f;
            szp_a += p1c;
            sfl_a += f7;
        }
    }

    // wrapped neighbor indexing + pres mask
    int nb8[9];
    unsigned pmask = 0;
    {
        int k = 0;
#pragma unroll
        for (int di = -1; di <= 1; ++di)
#pragma unroll
            for (int dj = -1; dj <= 1; ++dj, ++k) {
                int nc = ((i + di) & 15) * 16 + ((j + dj) & 15);
                nb8[k] = nc << 3;
                if (p1s[nc] > THRS) pmask |= (1u << k);
            }
    }

    // ---- tensor-core dot phase: D = s0 . s1^T band, 4 chunks of 4 row-groups ----
    float dotf[9] = {0.f, 0.f, 0.f, 0.f, 0.f, 0.f, 0.f, 0.f, 0.f};
    {
        unsigned s0u = (unsigned)__cvta_generic_to_shared(s0b);
        unsigned s1u = (unsigned)__cvta_generic_to_shared(s1b);
        int gi_local = wid >> 1;        // 0..3: group within chunk
        int nthalf = wid & 1;           // this warp covers nt = 3*nthalf + {0,1,2}
        int alane15 = lane & 15;
        int ah = (lane >= 16) ? 1 : 0;  // A k-half
        int bh = (lane >= 8) ? 1 : 0;   // B k-half
        int blane7 = lane & 7;

#pragma unroll
        for (int ch = 0; ch < 4; ++ch) {
            int gi = ch * 4 + gi_local;
            float d[3][4];
#pragma unroll
            for (int nt = 0; nt < 3; ++nt)
                d[nt][0] = d[nt][1] = d[nt][2] = d[nt][3] = 0.f;

#pragma unroll
            for (int s = 0; s < 4; ++s) {
                int acell = gi * 16 + alane15;
                unsigned aaddr = s0u + ((unsigned)((acell << 3) + (((2 * s + ah)) ^ (acell & 7))) << 4);
                unsigned a0, a1, a2, a3;
                asm volatile("ldmatrix.sync.aligned.m8n8.x4.shared.b16 {%0,%1,%2,%3}, [%4];"
                             : "=r"(a0), "=r"(a1), "=r"(a2), "=r"(a3) : "r"(aaddr));
#pragma unroll
                for (int nt = 0; nt < 3; ++nt) {
                    int cidx = (nthalf * 3 + nt) * 8 + blane7;
                    int iw = (gi + (cidx >> 4) + 15) & 15;
                    int cellp = iw * 16 + (cidx & 15);
                    unsigned baddr = s1u + ((unsigned)((cellp << 3) + ((2 * s + bh) ^ (cellp & 7))) << 4);
                    unsigned b0, b1;
                    asm volatile("ldmatrix.sync.aligned.m8n8.x2.shared.b16 {%0,%1}, [%2];"
                                 : "=r"(b0), "=r"(b1) : "r"(baddr));
                    asm volatile("mma.sync.aligned.m16n8k16.row.col.f32.f16.f16.f32 "
                                 "{%0,%1,%2,%3}, {%4,%5,%6,%7}, {%8,%9}, {%0,%1,%2,%3};"
                                 : "+f"(d[nt][0]), "+f"(d[nt][1]), "+f"(d[nt][2]), "+f"(d[nt][3])
                                 : "r"(a0), "r"(a1), "r"(a2), "r"(a3), "r"(b0), "r"(b1));
                }
            }
            // epilogue: D rows local to chunk (64 rows), fp16, stride 26 u32
            int lrow = gi_local * 16 + (lane >> 2);
#pragma unroll
            for (int nt = 0; nt < 3; ++nt) {
                int cu = (nthalf * 3 + nt) * 4 + (lane & 3);
                Dsm[lrow * D_STRIDE + cu] = pkh(d[nt][0], d[nt][1]);
                Dsm[(lrow + 8) * D_STRIDE + cu] = pkh(d[nt][2], d[nt][3]);
            }
            __syncthreads();
            // owner threads of this chunk snapshot their 9 dots
            if ((tid >> 6) == ch) {
                const __half* Dr = (const __half*)Dsm + (tid & 63) * (2 * D_STRIDE);
#pragma unroll
                for (int k = 0; k < 9; ++k) {
                    int col = (k / 3) * 16 + ((j + (k % 3) - 1) & 15);
                    dotf[k] = __half2float(Dr[col]);
                }
            }
            __syncthreads();
        }
    }

    // ---- transform loop: prior norm + in-place COLUMN-MAX of |s0|*p0 ----
    unsigned pna = 0u, pnb = 0u;
#pragma unroll
    for (int q = 0; q < 8; ++q) {
        int off = q ^ cx;
        uint4 pu = s0b[cb + off];
        const unsigned* pw = (const unsigned*)&pu;
        pna = hfma2(pw[0], pw[0], pna);
        pnb = hfma2(pw[1], pw[1], pnb);
        pna = hfma2(pw[2], pw[2], pna);
        pnb = hfma2(pw[3], pw[3], pnb);
        uint4 tw;
        unsigned* twp = (unsigned*)&tw;
        twp[0] = hmul2(pw[0] & 0x7FFF7FFFu, z0h);
        twp[1] = hmul2(pw[1] & 0x7FFF7FFFu, z0h);
        twp[2] = hmul2(pw[2] & 0x7FFF7FFFu, z0h);
        twp[3] = hmul2(pw[3] & 0x7FFF7FFFu, z0h);
        uint4 cm;
        unsigned* cmp = (unsigned*)&cm;
#pragma unroll
        for (int w = 0; w < 4; ++w) {
            unsigned lv = __shfl_sync(0xffffffffu, twp[w], lsrc) & lmsk;
            unsigned rv = __shfl_sync(0xffffffffu, twp[w], rsrc) & rmsk;
            cmp[w] = hmax2(hmax2(lv, twp[w]), rv);
        }
        s0b[cb + off] = cm;
    }
    float pn = hsum(pna) + hsum(pnb);
    __syncthreads();   // all rows hold column-max now

    // clamped row indices: out-of-grid -> zero row (cell GG)
    int rup = ((i > 0)  ? c - 16 : GG) << 3;
    int rdn = ((i < 15) ? c + 16 : GG) << 3;
    int rux = (rup >> 3) & 7, rdx = (rdn >> 3) & 7;

    // ---- loop B: row-max of column-max + pool partials + cn ----
    unsigned cna = 0u, pda = 0u, naa = 0u;
#pragma unroll
    for (int q = 0; q < 8; ++q) {
        uint4 cu = s1b[cb + (q ^ cx)];
        const unsigned* cw = (const unsigned*)&cu;
        uint4 su = s0b[rup + (q ^ rux)];
        uint4 sc = s0b[cb + (q ^ cx)];
        uint4 sd = s0b[rdn + (q ^ rdx)];
        const unsigned* uu = (const unsigned*)&su;
        const unsigned* ucn = (const unsigned*)&sc;
        const unsigned* ud = (const unsigned*)&sd;
#pragma unroll
        for (int w = 0; w < 4; ++w) {
            unsigned ca = cw[w] & 0x7FFF7FFFu;
            cna = hfma2(ca, ca, cna);
            unsigned mb = hmax2(hmax2(uu[w], ucn[w]), ud[w]);
            pda = hfma2(mb, ca, pda);
            naa = hfma2(mb, mb, naa);
        }
    }
    float cn = hsum(cna), pd = hsum(pda), na = hsum(naa);

    n1s[c] = fminf(rsqrtf(cn), 1e8f);
    __syncthreads();

    float rpn = fminf(rsqrtf(pn), 1e8f);
    float ssum = 0.f, smax = -INFINITY;
#pragma unroll
    for (int k = 0; k < 9; ++k) {
        float s = dotf[k] * rpn * n1s[nb8[k] >> 3];
        if (pmask & (1u << k)) {
            ssum += s;
            smax = fmaxf(smax, s);
        }
    }
    if (p0c > THRS && pmask) obj_a += -5.0f * smax + ssum;
    float nb = fmaxf(p1c * sqrtf(cn), 1e-6f);
    float cosp = __fdividef(pd * p1c, fmaxf(sqrtf(na), 1e-6f) * nb);
    pool_a += -cosp * 0.5f * (p0c + p1c);
}

// Heavy blocks [0, 3B): pairs (2g, 2g+1), 3 frame loads for 2 pairs.
// Light blocks [3B, 4B): pair t=6 (+ image 7). Last block finalizes.
__global__ __launch_bounds__(256, 3) void fused_kernel(const float* __restrict__ zw,
                                                       const float* __restrict__ zp,
                                                       const float* __restrict__ fl,
                                                       const void* __restrict__ gs,
                                                       float* __restrict__ out,
                                                       int B) {
    extern __shared__ char smraw[];
    __shared__ double rd[7];
    __shared__ unsigned isLast;
    int tid = threadIdx.x;
    int blk = blockIdx.x;
    int slot = blk & 15;
    if (tid < 7) rd[tid] = 0.0;

    uint4* bufA = (uint4*)smraw;
    uint4* bufB = bufA + S0_ROWS * 8;
    unsigned* Dsm = (unsigned*)(bufB + S0_ROWS * 8);
    float* pA = (float*)(Dsm + 64 * D_STRIDE);
    float* pB = pA + GG;
    float* n1s = pB + GG;

    int nheavy = 3 * B;
    bool heavy = blk < nheavy;
    int b = heavy ? (blk % B) : (blk - nheavy);
    int t0 = heavy ? 2 * (blk / B) : (TT - 2);
    size_t f0 = (size_t)(t0 * B + b);

    if (tid < 32) ((unsigned*)(bufA + GG * 8))[tid] = 0u;
    else if (tid < 64) ((unsigned*)(bufB + GG * 8))[tid - 32] = 0u;
    pA[tid] = zp[f0 * GG + tid];
    pB[tid] = zp[(f0 + B) * GG + tid];

    // ---- load phase 1: frames t0, t0+1 (exact fp32 wl) ----
    const float4* g0 = (const float4*)(zw + f0 * (GG * DD));
    const float4* g1 = (const float4*)(zw + (f0 + B) * (GG * DD));
    const u64 NEG1 = 0xBF800000BF800000ULL;
    u64 wl2 = 0ULL;
#pragma unroll
    for (int it = 0; it < 16; ++it) {
        int idx = it * 256 + tid;
        float4 a = g0[idx];
        float4 v = g1[idx];
        u64 d01 = ffma2(mkf(a.x, a.y), NEG1, mkf(v.x, v.y));
        u64 d23 = ffma2(mkf(a.z, a.w), NEG1, mkf(v.z, v.w));
        wl2 = ffma2(d01, d01, wl2);
        wl2 = ffma2(d23, d23, wl2);
        int cell = idx >> 4, d4 = idx & 15;
        int u2idx = SWZ(cell, d4 >> 1) * 2 + (d4 & 1);
        uint2 pa, pb;
        pa.x = pkh(a.x, a.y);  pa.y = pkh(a.z, a.w);
        pb.x = pkh(v.x, v.y);  pb.y = pkh(v.z, v.w);
        ((uint2*)bufA)[u2idx] = pa;
        ((uint2*)bufB)[u2idx] = pb;
    }
    float wl = lohisum(wl2);
    __syncthreads();

    float pool_a = 0.f, obj_a = 0.f, pres_a = 0.f, fsq_a = 0.f, szp_a = 0.f, sfl_a = 0.f;

    process_pair(bufA, bufB, Dsm, pA, pB, n1s, zp, fl, B, t0, f0, tid,
                 pool_a, obj_a, pres_a, fsq_a, szp_a, sfl_a);

    if (heavy) {
        __syncthreads();

        // ---- load phase 2: frame t0+2 into bufA; wl vs fp16 bufB ----
        const float4* g2 = (const float4*)(zw + (f0 + 2 * B) * (GG * DD));
        float wlh = 0.f;
#pragma unroll
        for (int it = 0; it < 16; ++it) {
            int idx = it * 256 + tid;
            float4 cc = g2[idx];
            unsigned c01 = pkh(cc.x, cc.y), c23 = pkh(cc.z, cc.w);
            int cell = idx >> 4, d4 = idx & 15;
            int u2idx = SWZ(cell, d4 >> 1) * 2 + (d4 & 1);
            uint2 bv = ((const uint2*)bufB)[u2idx];
            wlh = sq2acc(hsub2(c01, bv.x), wlh);
            wlh = sq2acc(hsub2(c23, bv.y), wlh);
            ((uint2*)bufA)[u2idx] = make_uint2(c01, c23);
        }
        wl += wlh;
        pA[tid] = zp[(f0 + 2 * B) * GG + tid];
        __syncthreads();

        process_pair(bufB, bufA, Dsm, pB, pA, n1s, zp, fl, B, t0 + 1, f0 + B, tid,
                     pool_a, obj_a, pres_a, fsq_a, szp_a, sfl_a);
    }

    wl = wsum(wl); pool_a = wsum(pool_a); obj_a = wsum(obj_a);
    pres_a = wsum(pres_a); fsq_a = wsum(fsq_a); szp_a = wsum(szp_a); sfl_a = wsum(sfl_a);
    if ((tid & 31) == 0) {
        atomicAdd(&rd[0], (double)wl);
        atomicAdd(&rd[1], (double)pool_a);
        atomicAdd(&rd[2], (double)obj_a);
        atomicAdd(&rd[3], (double)pres_a);
        atomicAdd(&rd[4], (double)fsq_a);
        atomicAdd(&rd[5], (double)szp_a);
        atomicAdd(&rd[6], (double)sfl_a);
    }
    __syncthreads();
    if (tid == 0) {
#pragma unroll
        for (int q = 0; q < 7; ++q) atomicAdd(&g_slot[q][slot], rd[q]);
    }

    if (tid == 0) {
        __threadfence();
        unsigned old = atomicAdd(&g_ctr, 1u);
        isLast = (old == gridDim.x - 1u) ? 1u : 0u;
    }
    __syncthreads();

    if (isLast && tid == 0) {
        __threadfence();
        double acc[7];
#pragma unroll
        for (int q = 0; q < 7; ++q) {
            double s = 0.0;
#pragma unroll
            for (int r = 0; r < 16; ++r) { s += g_slot[q][r]; g_slot[q][r] = 0.0; }
            acc[q] = s;
        }
        g_ctr = 0u;

        int gi = *(const int*)gs;
        double gstep = (gi < 0 || gi > 1000000000) ? (double)__int_as_float(gi) : (double)gi;

        double scale_obj = gstep / 200000.0;        if (scale_obj > 1.0) scale_obj = 1.0;
        double scale_flow = 1.0 - gstep / 100000.0; if (scale_flow < 0.0) scale_flow = 0.0;

        double hinge = acc[5] - acc[6];
        if (hinge < 0.0) hinge = 0.0;
        double flow_loss = acc[4] + 100.0 * hinge;

        double loss = acc[0]
                    + acc[3]
                    + acc[1]
                    + acc[2] * scale_obj * 10.0
                    + flow_loss * scale_flow;
        out[0] = (float)loss;
    }
}

extern "C" void kernel_launch(void* const* d_in, const int* in_sizes, int n_in,
                              void* d_out, int out_size) {
    const float* zw = (const float*)d_in[0];
    const float* zp = (const float*)d_in[1];
    const float* fl = (const float*)d_in[2];
    const void*  gs = d_in[3];
    int B = in_sizes[0] / (TT * GG * DD);

    static int configured = 0;
    if (!configured) {
        cudaFuncSetAttribute(fused_kernel, cudaFuncAttributeMaxDynamicSharedMemorySize, SMEM_BYTES);
        configured = 1;
    }

    fused_kernel<<<4 * B, 256, SMEM_BYTES>>>(zw, zp, fl, gs, (float*)d_out, B);
}